// round 8
// baseline (speedup 1.0000x reference)
#include <cuda_runtime.h>
#include <math.h>
#include <stdint.h>

#define L_TOT  65536
#define HDIM   256
#define WDIM   256
#define DIM    192
#define C1     48
#define NTOK   8

typedef unsigned long long u64t;

__device__ __forceinline__ u64t ffma2(u64t a, u64t b, u64t c) {
    u64t d;
    asm("fma.rn.f32x2 %0, %1, %2, %3;" : "=l"(d) : "l"(a), "l"(b), "l"(c));
    return d;
}
union F2u { u64t u; float2 f; };
__device__ __forceinline__ float lohi_sum(u64t v) { F2u t; t.u = v; return t.f.x + t.f.y; }
__device__ __forceinline__ float lo_of(u64t v) { F2u t; t.u = v; return t.f.x; }
__device__ __forceinline__ float hi_of(u64t v) { F2u t; t.u = v; return t.f.y; }

// ---------------- scratch ----------------
__device__ float  g_intensity[L_TOT];
__device__ float  g_f1[(size_t)C1 * L_TOT];    // conv1 out [ic][l]
__device__ float  g_feat[(size_t)L_TOT * DIM]; // conv2 out [l][c]
__device__ float  g_gamma[L_TOT];
__device__ float  g_beta[L_TOT];
__device__ float2 g_w2d[432 * 192];            // conv2 w dup: [k][oc] = (w,w), k = ic*9+kp
__device__ float2 g_owt[96 * 192];             // out_w k-pairs: [kp][o] = (w[o][2kp], w[o][2kp+1])

// ---------------- K0: weight prep ----------------
__global__ void k_prep(const float* __restrict__ w2, const float* __restrict__ out_w) {
    int idx = blockIdx.x * 256 + threadIdx.x;
    if (idx < 82944) {
        int k = idx / 192, oc = idx - k * 192;
        float w = w2[(size_t)oc * 432 + k];
        g_w2d[idx] = make_float2(w, w);
    } else {
        int j = idx - 82944;
        if (j < 18432) {
            int kp = j / 192, o = j - kp * 192;
            g_owt[j] = make_float2(out_w[o * DIM + kp * 2], out_w[o * DIM + kp * 2 + 1]);
        }
    }
}

// ---------------- K1: intensity ----------------
__global__ void k_intensity(const float* __restrict__ x) {
    int l = blockIdx.x * 256 + threadIdx.x;
    const float* p = x + (size_t)l * DIM;
    g_intensity[l] = 0.299f * p[0] + 0.587f * p[1] + 0.114f * p[2];
}

// ---------------- K2: conv1 1->48, 3x3 SAME, LeakyReLU(0.2) ----------------
__global__ void k_conv1(const float* __restrict__ w, const float* __restrict__ b) {
    int l  = blockIdx.x * 256 + threadIdx.x;
    int oc = blockIdx.y;
    int y = l >> 8, xx = l & 255;
    float acc = b[oc];
    #pragma unroll
    for (int ky = 0; ky < 3; ky++) {
        int gy = y + ky - 1;
        if (gy < 0 || gy >= HDIM) continue;
        #pragma unroll
        for (int kx = 0; kx < 3; kx++) {
            int gx = xx + kx - 1;
            if (gx < 0 || gx >= WDIM) continue;
            acc += w[oc * 9 + ky * 3 + kx] * g_intensity[(gy << 8) + gx];
        }
    }
    acc = (acc > 0.f) ? acc : 0.2f * acc;
    g_f1[(size_t)oc * L_TOT + l] = acc;
}

// ---------------- K3: conv2 48->192 (pixel-pair f32x2, dup weights) ----------------
// Block: 256 pix (one image row) x 64 oc, 256 thr (8 tx oc-groups x 32 ty).
// Thread: 8 pix (4 pairs) x 8 oc. Per tap: a=4 LDS.64 (32B), b=4 LDS.128 dup-w (64B),
// 32 ffma2 (64 MACs) -> 1.5 B/MAC. Double-buffered per-ic staging, 1 sync/ic.
__global__ __launch_bounds__(256, 2) void k_conv2(const float* __restrict__ b2) {
    __shared__ __align__(16) float2 Ws[2][9][64];   // dup weights [kp][oc-local]
    __shared__ __align__(16) float  Ps[2][9][256];  // shifted pixel rows [kp][p]
    int tid = threadIdx.x;
    int oc0 = (blockIdx.x % 3) * 64;
    int y   = blockIdx.x / 3;          // image row
    int tx = tid & 7;    // oc group: oc0 + tx*8 + j
    int ty = tid >> 3;   // pixel group: ty*8 + 0..7

    u64t acc[4][8];
    #pragma unroll
    for (int i = 0; i < 4; i++)
        #pragma unroll
        for (int j = 0; j < 8; j++) acc[i][j] = 0ull;

    auto stage = [&](int ic, int buf) {
        for (int idx = tid; idx < 576; idx += 256) {
            int kp = idx >> 6, ocl = idx & 63;
            Ws[buf][kp][ocl] = g_w2d[(ic * 9 + kp) * 192 + oc0 + ocl];
        }
        #pragma unroll
        for (int rep = 0; rep < 9; rep++) {
            int idx = rep * 256 + tid;
            int kp = idx >> 8, p = idx & 255;
            int ky = kp / 3, kx = kp - ky * 3;
            int gy = y + ky - 1, gx = p + kx - 1;
            float v = 0.f;
            if (gy >= 0 && gy < HDIM && gx >= 0 && gx < WDIM)
                v = g_f1[(size_t)ic * L_TOT + (gy << 8) + gx];
            Ps[buf][kp][p] = v;
        }
    };

    stage(0, 0);
    __syncthreads();
    for (int ic = 0; ic < C1; ic++) {
        int buf = ic & 1;
        if (ic + 1 < C1) stage(ic + 1, buf ^ 1);
        #pragma unroll
        for (int kp = 0; kp < 9; kp++) {
            u64t a[4];
            #pragma unroll
            for (int i = 0; i < 4; i++)
                a[i] = *(const u64t*)&Ps[buf][kp][ty * 8 + 2 * i];
            const ulonglong2* bp = (const ulonglong2*)&Ws[buf][kp][tx * 8];
            ulonglong2 b0 = bp[0], b1 = bp[1], b2v = bp[2], b3 = bp[3];
            u64t bv[8] = {b0.x, b0.y, b1.x, b1.y, b2v.x, b2v.y, b3.x, b3.y};
            #pragma unroll
            for (int i = 0; i < 4; i++)
                #pragma unroll
                for (int j = 0; j < 8; j++)
                    acc[i][j] = ffma2(a[i], bv[j], acc[i][j]);
        }
        __syncthreads();
    }

    float bj[8];
    #pragma unroll
    for (int j = 0; j < 8; j++) bj[j] = b2[oc0 + tx * 8 + j];
    #pragma unroll
    for (int i = 0; i < 4; i++) {
        int l0p = (y << 8) + ty * 8 + 2 * i;
        float* op0 = g_feat + (size_t)l0p * DIM + oc0 + tx * 8;
        float* op1 = op0 + DIM;
        float r0[8], r1[8];
        #pragma unroll
        for (int j = 0; j < 8; j++) { r0[j] = lo_of(acc[i][j]) + bj[j]; r1[j] = hi_of(acc[i][j]) + bj[j]; }
        *(float4*)(op0 + 0) = make_float4(r0[0], r0[1], r0[2], r0[3]);
        *(float4*)(op0 + 4) = make_float4(r0[4], r0[5], r0[6], r0[7]);
        *(float4*)(op1 + 0) = make_float4(r1[0], r1[1], r1[2], r1[3]);
        *(float4*)(op1 + 4) = make_float4(r1[4], r1[5], r1[6], r1[7]);
    }
}

// ---------------- K4: routing MLP + softmax + gumbel argmax (R1-proven) ----------
__global__ __launch_bounds__(256) void k_route(const float* __restrict__ x,
                                               const float* __restrict__ w1,
                                               const float* __restrict__ b1,
                                               const float* __restrict__ w2,
                                               const float* __restrict__ b2r,
                                               const float* __restrict__ gumbel,
                                               const float* __restrict__ emb) {
    __shared__ float z_s[64][17];
    __shared__ float W1s[16][97];
    __shared__ float hm_s[64][97];
    __shared__ float W2s[8][96];
    __shared__ float lg_s[64][9];
    int tid = threadIdx.x;
    int t0base = blockIdx.x * 64;
    int tx = tid & 15;
    int ty = tid >> 4;

    for (int idx = tid; idx < 768; idx += 256)
        W2s[idx / 96][idx % 96] = w2[idx];

    float acc[4][6];
    #pragma unroll
    for (int i = 0; i < 4; i++)
        #pragma unroll
        for (int jj = 0; jj < 6; jj++) acc[i][jj] = 0.f;

    for (int k0 = 0; k0 < DIM; k0 += 16) {
        __syncthreads();
        for (int idx = tid; idx < 1024; idx += 256) {
            int tok = idx >> 4, kk = idx & 15;
            size_t off = (size_t)(t0base + tok) * DIM + k0 + kk;
            z_s[tok][kk] = x[off] + 0.3f * g_feat[off];
        }
        for (int idx = tid; idx < 1536; idx += 256) {
            int j = idx >> 4, kk = idx & 15;
            W1s[kk][j] = w1[j * DIM + k0 + kk];
        }
        __syncthreads();
        #pragma unroll
        for (int kk = 0; kk < 16; kk++) {
            float a[4], b[6];
            #pragma unroll
            for (int i = 0; i < 4; i++) a[i] = z_s[ty * 4 + i][kk];
            #pragma unroll
            for (int jj = 0; jj < 6; jj++) b[jj] = W1s[kk][tx * 6 + jj];
            #pragma unroll
            for (int i = 0; i < 4; i++)
                #pragma unroll
                for (int jj = 0; jj < 6; jj++) acc[i][jj] += a[i] * b[jj];
        }
    }
    __syncthreads();
    #pragma unroll
    for (int jj = 0; jj < 6; jj++) {
        float bb = b1[tx * 6 + jj];
        #pragma unroll
        for (int i = 0; i < 4; i++) {
            float v = acc[i][jj] + bb;
            v = 0.5f * v * (1.0f + erff(v * 0.7071067811865476f));
            hm_s[ty * 4 + i][tx * 6 + jj] = v;
        }
    }
    __syncthreads();
    #pragma unroll
    for (int half = 0; half < 2; half++) {
        int tok = (tid >> 3) + half * 32;
        int t = tid & 7;
        float s = b2r[t];
        #pragma unroll 8
        for (int j = 0; j < 96; j++) s += hm_s[tok][j] * W2s[t][j];
        lg_s[tok][t] = s;
    }
    __syncthreads();
    if (tid < 64) {
        int tok = tid;
        int l = t0base + tok;
        float mx = -1e30f;
        #pragma unroll
        for (int t = 0; t < NTOK; t++) mx = fmaxf(mx, lg_s[tok][t]);
        float e[NTOK], sum = 0.f;
        #pragma unroll
        for (int t = 0; t < NTOK; t++) { e[t] = expf(lg_s[tok][t] - mx); sum += e[t]; }
        float inv = 1.0f / sum;
        float inten = g_intensity[l];
        float best = -1e30f; int kbest = 0; float rw0 = 0.f;
        #pragma unroll
        for (int t = 0; t < NTOK; t++) {
            float rw = e[t] * inv;
            if (t == 0) rw0 = rw;
            float sim = 1.0f - fabsf(emb[t] - inten);
            float u = gumbel[(size_t)l * NTOK + t];
            u = fmaxf(u, 1e-10f);
            float g = -logf(-logf(u));
            float sc = rw * sim + g;
            if (sc > best) { best = sc; kbest = t; }
        }
        float ek = emb[kbest];
        g_gamma[l] = 0.3f + 0.7f / (1.0f + expf(-ek));
        g_beta[l]  = rw0 - 0.5f;
    }
}

// ---------------- K5: v=D*(gamma*x+beta), LayerNorm, out = yn@out_w^T + b ----------
// 64 tok/block, 256 thr (16 tx x 16 ty). Thread: 4 tok x 12 oc (oc = tx+16j),
// k-pair f32x2 via g_owt. 128 B smem / 96 MACs per kp = 1.33 B/MAC.
__global__ __launch_bounds__(256, 2) void k_final(const float* __restrict__ x,
                                                  const float* __restrict__ Dv,
                                                  const float* __restrict__ ln_w,
                                                  const float* __restrict__ ln_b,
                                                  const float* __restrict__ out_b,
                                                  float* __restrict__ out) {
    extern __shared__ float sh[];
    float*  v_s  = sh;                           // [64][196]
    u64t*   Bs   = (u64t*)(sh + 64 * 196);       // [16][192] k-pair weights
    float*  mu_s = sh + 64 * 196 + 16 * 192 * 2; // [64]
    float*  rs_s = mu_s + 64;                    // [64]

    int tid = threadIdx.x;
    int l0 = blockIdx.x * 64;
    int tx = tid & 15;   // oc lane: oc = tx + 16*j
    int ty = tid >> 4;   // tok: ty*4 + i

    for (int idx = tid; idx < 3072; idx += 256) {
        int tok = idx / 48, c4 = idx % 48;
        int l = l0 + tok;
        float4 xv = *(const float4*)&x[(size_t)l * DIM + c4 * 4];
        float4 dv = *(const float4*)&Dv[c4 * 4];
        float g = g_gamma[l], b = g_beta[l];
        float4 v;
        v.x = dv.x * (g * xv.x + b); v.y = dv.y * (g * xv.y + b);
        v.z = dv.z * (g * xv.z + b); v.w = dv.w * (g * xv.w + b);
        *(float4*)&v_s[tok * 196 + c4 * 4] = v;
    }
    __syncthreads();
    {
        int tok = tid >> 2, l4 = tid & 3;
        float s = 0.f, sq = 0.f;
        for (int c = l4; c < DIM; c += 4) {
            float v = v_s[tok * 196 + c];
            s += v; sq += v * v;
        }
        s  += __shfl_down_sync(0xffffffffu, s, 2);
        sq += __shfl_down_sync(0xffffffffu, sq, 2);
        s  += __shfl_down_sync(0xffffffffu, s, 1);
        sq += __shfl_down_sync(0xffffffffu, sq, 1);
        if (l4 == 0) {
            float mu = s * (1.0f / DIM);
            float var = sq * (1.0f / DIM) - mu * mu;
            mu_s[tok] = mu;
            rs_s[tok] = rsqrtf(var + 1e-5f);
        }
    }
    __syncthreads();
    for (int idx = tid; idx < 3072; idx += 256) {
        int tok = idx / 48, c4 = idx % 48;
        float4 v = *(const float4*)&v_s[tok * 196 + c4 * 4];
        float4 lw = *(const float4*)&ln_w[c4 * 4];
        float4 lb = *(const float4*)&ln_b[c4 * 4];
        float mu = mu_s[tok], rs = rs_s[tok];
        v.x = (v.x - mu) * rs * lw.x + lb.x; v.y = (v.y - mu) * rs * lw.y + lb.y;
        v.z = (v.z - mu) * rs * lw.z + lb.z; v.w = (v.w - mu) * rs * lw.w + lb.w;
        *(float4*)&v_s[tok * 196 + c4 * 4] = v;
    }

    u64t acc[4][12];
    #pragma unroll
    for (int i = 0; i < 4; i++)
        #pragma unroll
        for (int j = 0; j < 12; j++) acc[i][j] = 0ull;

    for (int kc = 0; kc < 6; kc++) {
        __syncthreads();
        for (int idx = tid; idx < 3072; idx += 256)
            Bs[idx] = ((const u64t*)g_owt)[kc * 3072 + idx];
        __syncthreads();
        #pragma unroll
        for (int kp = 0; kp < 16; kp++) {
            u64t a[4];
            #pragma unroll
            for (int i = 0; i < 4; i++)
                a[i] = *(const u64t*)&v_s[(ty * 4 + i) * 196 + kc * 32 + kp * 2];
            #pragma unroll
            for (int j = 0; j < 12; j++) {
                u64t bv = Bs[kp * 192 + tx + 16 * j];
                #pragma unroll
                for (int i = 0; i < 4; i++)
                    acc[i][j] = ffma2(a[i], bv, acc[i][j]);
            }
        }
    }

    float bb[12];
    #pragma unroll
    for (int j = 0; j < 12; j++) bb[j] = out_b[tx + 16 * j];
    #pragma unroll
    for (int i = 0; i < 4; i++) {
        int l = l0 + ty * 4 + i;
        float* op = out + (size_t)l * DIM;
        #pragma unroll
        for (int j = 0; j < 12; j++)
            op[tx + 16 * j] = lohi_sum(acc[i][j]) + bb[j];
    }
}

// ---------------- launch ----------------
extern "C" void kernel_launch(void* const* d_in, const int* in_sizes, int n_in,
                              void* d_out, int out_size) {
    const float* x        = (const float*)d_in[0];
    const float* gumbel_u = (const float*)d_in[1];
    const float* conv1_w  = (const float*)d_in[2];
    const float* conv1_b  = (const float*)d_in[3];
    const float* conv2_w  = (const float*)d_in[4];
    const float* conv2_b  = (const float*)d_in[5];
    const float* route1_w = (const float*)d_in[6];
    const float* route1_b = (const float*)d_in[7];
    const float* route2_w = (const float*)d_in[8];
    const float* route2_b = (const float*)d_in[9];
    const float* Dv       = (const float*)d_in[11];
    const float* ln_w     = (const float*)d_in[12];
    const float* ln_b     = (const float*)d_in[13];
    const float* out_w    = (const float*)d_in[14];
    const float* out_b    = (const float*)d_in[15];
    const float* emb      = (const float*)d_in[16];
    float* out = (float*)d_out;

    int final_smem = (64 * 196 + 16 * 192 * 2 + 128 + 16) * (int)sizeof(float);
    static int attr_done = 0;
    if (!attr_done) {
        cudaFuncSetAttribute(k_final, cudaFuncAttributeMaxDynamicSharedMemorySize, final_smem);
        attr_done = 1;
    }

    k_prep<<<(82944 + 18432 + 255) / 256, 256>>>(conv2_w, out_w);
    k_intensity<<<L_TOT / 256, 256>>>(x);
    k_conv1<<<dim3(L_TOT / 256, C1), 256>>>(conv1_w, conv1_b);
    k_conv2<<<3 * HDIM, 256>>>(conv2_b);
    k_route<<<L_TOT / 64, 256>>>(x, route1_w, route1_b, route2_w, route2_b,
                                 gumbel_u, emb);
    k_final<<<L_TOT / 64, 256, final_smem>>>(x, Dv, ln_w, ln_b, out_b, out);
}

// round 10
// speedup vs baseline: 1.5163x; 1.5163x over previous
#include <cuda_runtime.h>
#include <math.h>
#include <stdint.h>

#define L_TOT  65536
#define HDIM   256
#define WDIM   256
#define DIM    192
#define C1     48
#define NTOK   8

typedef unsigned long long u64t;

__device__ __forceinline__ u64t ffma2(u64t a, u64t b, u64t c) {
    u64t d;
    asm("fma.rn.f32x2 %0, %1, %2, %3;" : "=l"(d) : "l"(a), "l"(b), "l"(c));
    return d;
}
union F2u { u64t u; float2 f; };
__device__ __forceinline__ float lohi_sum(u64t v) { F2u t; t.u = v; return t.f.x + t.f.y; }
__device__ __forceinline__ float lo_of(u64t v) { F2u t; t.u = v; return t.f.x; }
__device__ __forceinline__ float hi_of(u64t v) { F2u t; t.u = v; return t.f.y; }

// ---------------- scratch ----------------
__device__ float  g_intensity[L_TOT];
__device__ float  g_f1[(size_t)C1 * L_TOT];    // conv1 out [ic][l]
__device__ float  g_feat[(size_t)L_TOT * DIM]; // conv2 out [l][c]
__device__ float  g_gamma[L_TOT];
__device__ float  g_beta[L_TOT];
__device__ float2 g_w2d[432 * 192];            // conv2 w dup: [k][oc] = (w,w), k = ic*9+kp
__device__ float2 g_owt[96 * 192];             // out_w k-pairs: [kp][o] = (w[o][2kp], w[o][2kp+1])

// ---------------- K0: weight prep ----------------
__global__ void k_prep(const float* __restrict__ w2, const float* __restrict__ out_w) {
    int idx = blockIdx.x * 256 + threadIdx.x;
    if (idx < 82944) {
        int k = idx / 192, oc = idx - k * 192;
        float w = w2[(size_t)oc * 432 + k];
        g_w2d[idx] = make_float2(w, w);
    } else {
        int j = idx - 82944;
        if (j < 18432) {
            int kp = j / 192, o = j - kp * 192;
            g_owt[j] = make_float2(out_w[o * DIM + kp * 2], out_w[o * DIM + kp * 2 + 1]);
        }
    }
}

// ---------------- K1: intensity ----------------
__global__ void k_intensity(const float* __restrict__ x) {
    int l = blockIdx.x * 256 + threadIdx.x;
    const float* p = x + (size_t)l * DIM;
    g_intensity[l] = 0.299f * p[0] + 0.587f * p[1] + 0.114f * p[2];
}

// ---------------- K2: conv1 1->48, 3x3 SAME, LeakyReLU(0.2) ----------------
__global__ void k_conv1(const float* __restrict__ w, const float* __restrict__ b) {
    int l  = blockIdx.x * 256 + threadIdx.x;
    int oc = blockIdx.y;
    int y = l >> 8, xx = l & 255;
    float acc = b[oc];
    #pragma unroll
    for (int ky = 0; ky < 3; ky++) {
        int gy = y + ky - 1;
        if (gy < 0 || gy >= HDIM) continue;
        #pragma unroll
        for (int kx = 0; kx < 3; kx++) {
            int gx = xx + kx - 1;
            if (gx < 0 || gx >= WDIM) continue;
            acc += w[oc * 9 + ky * 3 + kx] * g_intensity[(gy << 8) + gx];
        }
    }
    acc = (acc > 0.f) ? acc : 0.2f * acc;
    g_f1[(size_t)oc * L_TOT + l] = acc;
}

// ---------------- K3: conv2 48->192 (pixel-pair f32x2, E/O shifted copies) --------
// Block: 128 pix x 64 oc, 256 thr (tx 0..15 oc-lanes, ty 0..15 pair-groups).
// Thread: 4 pix-pairs x 4 oc (oc = oc0 + tx + 16j).
// Per pixel row gy, two smem copies: E[q]=v(x0+q), O[q]=v(x0+q-1). All three
// kx-shifts become ALIGNED LDS.64: d=0 -> E[p], d=-1 -> O[p], d=+1 -> O[p+2].
// Per tap: 4 a-LDS.64 + 4 b-LDS.64 (dup weights, 1 wavefront) + 16 ffma2.
__global__ __launch_bounds__(256, 3) void k_conv2(const float* __restrict__ b2) {
    __shared__ __align__(16) float  Ps[2][3][264];  // [buf][row][E:0..127 | pad | O:132..261]
    __shared__ __align__(16) float2 Ws[2][9][64];   // dup weights [kp][oc-local]
    int tid = threadIdx.x;
    int bid = blockIdx.x;
    int oc0  = (bid % 3) * 64;
    int q    = bid / 3;
    int half = q & 1;
    int y    = q >> 1;
    int x0   = half << 7;
    int tx = tid & 15;   // oc lane: oc = oc0 + tx + 16*j
    int ty = tid >> 4;   // pair group: pairs ty*4 + i

    u64t acc[4][4];
    #pragma unroll
    for (int i = 0; i < 4; i++)
        #pragma unroll
        for (int j = 0; j < 4; j++) acc[i][j] = 0ull;

    auto stage = [&](int ic, int buf) {
        for (int idx = tid; idx < 576; idx += 256) {
            int kp = idx >> 6, ocl = idx & 63;
            Ws[buf][kp][ocl] = g_w2d[(ic * 9 + kp) * 192 + oc0 + ocl];
        }
        const float* f1 = g_f1 + (size_t)ic * L_TOT;
        #pragma unroll
        for (int r = 0; r < 3; r++) {
            int gy = y + r - 1;
            bool row_ok = (gy >= 0 && gy < HDIM);
            const float* frow = f1 + (gy << 8);
            for (int c = tid; c < 264; c += 256) {
                int gx = (c < 132) ? (x0 + c) : (x0 + c - 133);
                float v = 0.f;
                if (row_ok && gx >= 0 && gx < WDIM && !(c >= 128 && c < 132))
                    v = frow[gx];
                Ps[buf][r][c] = v;
            }
        }
    };

    stage(0, 0);
    __syncthreads();
    for (int ic = 0; ic < C1; ic++) {
        int buf = ic & 1;
        if (ic + 1 < C1) stage(ic + 1, buf ^ 1);
        #pragma unroll
        for (int ky = 0; ky < 3; ky++) {
            const float* E = &Ps[buf][ky][0];
            const float* O = E + 132;
            #pragma unroll
            for (int kx = 0; kx < 3; kx++) {
                int kp = ky * 3 + kx;
                u64t bv[4];
                #pragma unroll
                for (int j = 0; j < 4; j++)
                    bv[j] = *(const u64t*)&Ws[buf][kp][tx + 16 * j];
                const float* ap = (kx == 1) ? E : O;
                int ofs = (kx == 2) ? 2 : 0;
                u64t a[4];
                #pragma unroll
                for (int i = 0; i < 4; i++)
                    a[i] = *(const u64t*)&ap[(ty * 4 + i) * 2 + ofs];
                #pragma unroll
                for (int i = 0; i < 4; i++)
                    #pragma unroll
                    for (int j = 0; j < 4; j++)
                        acc[i][j] = ffma2(a[i], bv[j], acc[i][j]);
            }
        }
        __syncthreads();
    }

    float bj[4];
    #pragma unroll
    for (int j = 0; j < 4; j++) bj[j] = b2[oc0 + tx + 16 * j];
    #pragma unroll
    for (int i = 0; i < 4; i++) {
        int p = (ty * 4 + i) * 2;
        int l = (y << 8) + x0 + p;
        float* op0 = g_feat + (size_t)l * DIM + oc0;
        float* op1 = op0 + DIM;
        #pragma unroll
        for (int j = 0; j < 4; j++) {
            op0[tx + 16 * j] = lo_of(acc[i][j]) + bj[j];
            op1[tx + 16 * j] = hi_of(acc[i][j]) + bj[j];
        }
    }
}

// ---------------- K4: routing MLP + softmax + gumbel argmax (R1-proven) ----------
__global__ __launch_bounds__(256) void k_route(const float* __restrict__ x,
                                               const float* __restrict__ w1,
                                               const float* __restrict__ b1,
                                               const float* __restrict__ w2,
                                               const float* __restrict__ b2r,
                                               const float* __restrict__ gumbel,
                                               const float* __restrict__ emb) {
    __shared__ float z_s[64][17];
    __shared__ float W1s[16][97];
    __shared__ float hm_s[64][97];
    __shared__ float W2s[8][96];
    __shared__ float lg_s[64][9];
    int tid = threadIdx.x;
    int t0base = blockIdx.x * 64;
    int tx = tid & 15;
    int ty = tid >> 4;

    for (int idx = tid; idx < 768; idx += 256)
        W2s[idx / 96][idx % 96] = w2[idx];

    float acc[4][6];
    #pragma unroll
    for (int i = 0; i < 4; i++)
        #pragma unroll
        for (int jj = 0; jj < 6; jj++) acc[i][jj] = 0.f;

    for (int k0 = 0; k0 < DIM; k0 += 16) {
        __syncthreads();
        for (int idx = tid; idx < 1024; idx += 256) {
            int tok = idx >> 4, kk = idx & 15;
            size_t off = (size_t)(t0base + tok) * DIM + k0 + kk;
            z_s[tok][kk] = x[off] + 0.3f * g_feat[off];
        }
        for (int idx = tid; idx < 1536; idx += 256) {
            int j = idx >> 4, kk = idx & 15;
            W1s[kk][j] = w1[j * DIM + k0 + kk];
        }
        __syncthreads();
        #pragma unroll
        for (int kk = 0; kk < 16; kk++) {
            float a[4], b[6];
            #pragma unroll
            for (int i = 0; i < 4; i++) a[i] = z_s[ty * 4 + i][kk];
            #pragma unroll
            for (int jj = 0; jj < 6; jj++) b[jj] = W1s[kk][tx * 6 + jj];
            #pragma unroll
            for (int i = 0; i < 4; i++)
                #pragma unroll
                for (int jj = 0; jj < 6; jj++) acc[i][jj] += a[i] * b[jj];
        }
    }
    __syncthreads();
    #pragma unroll
    for (int jj = 0; jj < 6; jj++) {
        float bb = b1[tx * 6 + jj];
        #pragma unroll
        for (int i = 0; i < 4; i++) {
            float v = acc[i][jj] + bb;
            v = 0.5f * v * (1.0f + erff(v * 0.7071067811865476f));
            hm_s[ty * 4 + i][tx * 6 + jj] = v;
        }
    }
    __syncthreads();
    #pragma unroll
    for (int half = 0; half < 2; half++) {
        int tok = (tid >> 3) + half * 32;
        int t = tid & 7;
        float s = b2r[t];
        #pragma unroll 8
        for (int j = 0; j < 96; j++) s += hm_s[tok][j] * W2s[t][j];
        lg_s[tok][t] = s;
    }
    __syncthreads();
    if (tid < 64) {
        int tok = tid;
        int l = t0base + tok;
        float mx = -1e30f;
        #pragma unroll
        for (int t = 0; t < NTOK; t++) mx = fmaxf(mx, lg_s[tok][t]);
        float e[NTOK], sum = 0.f;
        #pragma unroll
        for (int t = 0; t < NTOK; t++) { e[t] = expf(lg_s[tok][t] - mx); sum += e[t]; }
        float inv = 1.0f / sum;
        float inten = g_intensity[l];
        float best = -1e30f; int kbest = 0; float rw0 = 0.f;
        #pragma unroll
        for (int t = 0; t < NTOK; t++) {
            float rw = e[t] * inv;
            if (t == 0) rw0 = rw;
            float sim = 1.0f - fabsf(emb[t] - inten);
            float u = gumbel[(size_t)l * NTOK + t];
            u = fmaxf(u, 1e-10f);
            float g = -logf(-logf(u));
            float sc = rw * sim + g;
            if (sc > best) { best = sc; kbest = t; }
        }
        float ek = emb[kbest];
        g_gamma[l] = 0.3f + 0.7f / (1.0f + expf(-ek));
        g_beta[l]  = rw0 - 0.5f;
    }
}

// ---------------- K5: v=D*(gamma*x+beta), LayerNorm, out = yn@out_w^T + b ----------
// 64 tok/block, 256 thr (16 tx x 16 ty). Thread: 4 tok x 12 oc (oc = tx+16j),
// k-pair f32x2 via g_owt. (proven in R8)
__global__ __launch_bounds__(256, 2) void k_final(const float* __restrict__ x,
                                                  const float* __restrict__ Dv,
                                                  const float* __restrict__ ln_w,
                                                  const float* __restrict__ ln_b,
                                                  const float* __restrict__ out_b,
                                                  float* __restrict__ out) {
    extern __shared__ float sh[];
    float*  v_s  = sh;                           // [64][196]
    u64t*   Bs   = (u64t*)(sh + 64 * 196);       // [16][192] k-pair weights
    float*  mu_s = sh + 64 * 196 + 16 * 192 * 2; // [64]
    float*  rs_s = mu_s + 64;                    // [64]

    int tid = threadIdx.x;
    int l0 = blockIdx.x * 64;
    int tx = tid & 15;   // oc lane: oc = tx + 16*j
    int ty = tid >> 4;   // tok: ty*4 + i

    for (int idx = tid; idx < 3072; idx += 256) {
        int tok = idx / 48, c4 = idx % 48;
        int l = l0 + tok;
        float4 xv = *(const float4*)&x[(size_t)l * DIM + c4 * 4];
        float4 dv = *(const float4*)&Dv[c4 * 4];
        float g = g_gamma[l], b = g_beta[l];
        float4 v;
        v.x = dv.x * (g * xv.x + b); v.y = dv.y * (g * xv.y + b);
        v.z = dv.z * (g * xv.z + b); v.w = dv.w * (g * xv.w + b);
        *(float4*)&v_s[tok * 196 + c4 * 4] = v;
    }
    __syncthreads();
    {
        int tok = tid >> 2, l4 = tid & 3;
        float s = 0.f, sq = 0.f;
        for (int c = l4; c < DIM; c += 4) {
            float v = v_s[tok * 196 + c];
            s += v; sq += v * v;
        }
        s  += __shfl_down_sync(0xffffffffu, s, 2);
        sq += __shfl_down_sync(0xffffffffu, sq, 2);
        s  += __shfl_down_sync(0xffffffffu, s, 1);
        sq += __shfl_down_sync(0xffffffffu, sq, 1);
        if (l4 == 0) {
            float mu = s * (1.0f / DIM);
            float var = sq * (1.0f / DIM) - mu * mu;
            mu_s[tok] = mu;
            rs_s[tok] = rsqrtf(var + 1e-5f);
        }
    }
    __syncthreads();
    for (int idx = tid; idx < 3072; idx += 256) {
        int tok = idx / 48, c4 = idx % 48;
        float4 v = *(const float4*)&v_s[tok * 196 + c4 * 4];
        float4 lw = *(const float4*)&ln_w[c4 * 4];
        float4 lb = *(const float4*)&ln_b[c4 * 4];
        float mu = mu_s[tok], rs = rs_s[tok];
        v.x = (v.x - mu) * rs * lw.x + lb.x; v.y = (v.y - mu) * rs * lw.y + lb.y;
        v.z = (v.z - mu) * rs * lw.z + lb.z; v.w = (v.w - mu) * rs * lw.w + lb.w;
        *(float4*)&v_s[tok * 196 + c4 * 4] = v;
    }

    u64t acc[4][12];
    #pragma unroll
    for (int i = 0; i < 4; i++)
        #pragma unroll
        for (int j = 0; j < 12; j++) acc[i][j] = 0ull;

    for (int kc = 0; kc < 6; kc++) {
        __syncthreads();
        for (int idx = tid; idx < 3072; idx += 256)
            Bs[idx] = ((const u64t*)g_owt)[kc * 3072 + idx];
        __syncthreads();
        #pragma unroll
        for (int kp = 0; kp < 16; kp++) {
            u64t a[4];
            #pragma unroll
            for (int i = 0; i < 4; i++)
                a[i] = *(const u64t*)&v_s[(ty * 4 + i) * 196 + kc * 32 + kp * 2];
            #pragma unroll
            for (int j = 0; j < 12; j++) {
                u64t bv = Bs[kp * 192 + tx + 16 * j];
                #pragma unroll
                for (int i = 0; i < 4; i++)
                    acc[i][j] = ffma2(a[i], bv, acc[i][j]);
            }
        }
    }

    float bb[12];
    #pragma unroll
    for (int j = 0; j < 12; j++) bb[j] = out_b[tx + 16 * j];
    #pragma unroll
    for (int i = 0; i < 4; i++) {
        int l = l0 + ty * 4 + i;
        float* op = out + (size_t)l * DIM;
        #pragma unroll
        for (int j = 0; j < 12; j++)
            op[tx + 16 * j] = lohi_sum(acc[i][j]) + bb[j];
    }
}

// ---------------- launch ----------------
extern "C" void kernel_launch(void* const* d_in, const int* in_sizes, int n_in,
                              void* d_out, int out_size) {
    const float* x        = (const float*)d_in[0];
    const float* gumbel_u = (const float*)d_in[1];
    const float* conv1_w  = (const float*)d_in[2];
    const float* conv1_b  = (const float*)d_in[3];
    const float* conv2_w  = (const float*)d_in[4];
    const float* conv2_b  = (const float*)d_in[5];
    const float* route1_w = (const float*)d_in[6];
    const float* route1_b = (const float*)d_in[7];
    const float* route2_w = (const float*)d_in[8];
    const float* route2_b = (const float*)d_in[9];
    const float* Dv       = (const float*)d_in[11];
    const float* ln_w     = (const float*)d_in[12];
    const float* ln_b     = (const float*)d_in[13];
    const float* out_w    = (const float*)d_in[14];
    const float* out_b    = (const float*)d_in[15];
    const float* emb      = (const float*)d_in[16];
    float* out = (float*)d_out;

    int final_smem = (64 * 196 + 16 * 192 * 2 + 128 + 16) * (int)sizeof(float);
    static int attr_done = 0;
    if (!attr_done) {
        cudaFuncSetAttribute(k_final, cudaFuncAttributeMaxDynamicSharedMemorySize, final_smem);
        attr_done = 1;
    }

    k_prep<<<(82944 + 18432 + 255) / 256, 256>>>(conv2_w, out_w);
    k_intensity<<<L_TOT / 256, 256>>>(x);
    k_conv1<<<dim3(L_TOT / 256, C1), 256>>>(conv1_w, conv1_b);
    k_conv2<<<6 * HDIM, 256>>>(conv2_b);
    k_route<<<L_TOT / 64, 256>>>(x, route1_w, route1_b, route2_w, route2_b,
                                 gumbel_u, emb);
    k_final<<<L_TOT / 64, 256, final_smem>>>(x, Dv, ln_w, ln_b, out_b, out);
}

// round 11
// speedup vs baseline: 1.7535x; 1.1564x over previous
#include <cuda_runtime.h>
#include <math.h>
#include <stdint.h>

#define L_TOT  65536
#define HDIM   256
#define WDIM   256
#define DIM    192
#define C1     48
#define NTOK   8
#define OROW   260   // padded shifted-row length

typedef unsigned long long u64t;

__device__ __forceinline__ u64t ffma2(u64t a, u64t b, u64t c) {
    u64t d;
    asm("fma.rn.f32x2 %0, %1, %2, %3;" : "=l"(d) : "l"(a), "l"(b), "l"(c));
    return d;
}
union F2u { u64t u; float2 f; };
__device__ __forceinline__ float lohi_sum(u64t v) { F2u t; t.u = v; return t.f.x + t.f.y; }
__device__ __forceinline__ float lo_of(u64t v) { F2u t; t.u = v; return t.f.x; }
__device__ __forceinline__ float hi_of(u64t v) { F2u t; t.u = v; return t.f.y; }

// ---------------- scratch ----------------
__device__ float  g_intensity[L_TOT];
__device__ float  g_f1[(size_t)C1 * L_TOT];          // conv1 out [ic][l] (E rows)
__device__ float  g_f1o[(size_t)C1 * HDIM * OROW];   // conv1 out shifted: [ic][y][q]=v(q-1), pads 0
__device__ float  g_feat[(size_t)L_TOT * DIM];       // conv2 out [l][c]
__device__ float  g_gamma[L_TOT];
__device__ float  g_beta[L_TOT];
__device__ float2 g_w2d[432 * 192];                  // conv2 w dup: [k][oc]=(w,w), k=ic*9+kp
__device__ float2 g_owt[96 * 192];                   // out_w k-pairs

// ---------------- K0: weight prep ----------------
__global__ void k_prep(const float* __restrict__ w2, const float* __restrict__ out_w) {
    int idx = blockIdx.x * 256 + threadIdx.x;
    if (idx < 82944) {
        int k = idx / 192, oc = idx - k * 192;
        float w = w2[(size_t)oc * 432 + k];
        g_w2d[idx] = make_float2(w, w);
    } else {
        int j = idx - 82944;
        if (j < 18432) {
            int kp = j / 192, o = j - kp * 192;
            g_owt[j] = make_float2(out_w[o * DIM + kp * 2], out_w[o * DIM + kp * 2 + 1]);
        }
    }
}

// ---------------- K1: intensity ----------------
__global__ void k_intensity(const float* __restrict__ x) {
    int l = blockIdx.x * 256 + threadIdx.x;
    const float* p = x + (size_t)l * DIM;
    g_intensity[l] = 0.299f * p[0] + 0.587f * p[1] + 0.114f * p[2];
}

// ---------------- K2: conv1 1->48, 3x3 SAME, LeakyReLU(0.2) ----------------
__global__ void k_conv1(const float* __restrict__ w, const float* __restrict__ b) {
    int l  = blockIdx.x * 256 + threadIdx.x;
    int oc = blockIdx.y;
    int y = l >> 8, xx = l & 255;
    float acc = b[oc];
    #pragma unroll
    for (int ky = 0; ky < 3; ky++) {
        int gy = y + ky - 1;
        if (gy < 0 || gy >= HDIM) continue;
        #pragma unroll
        for (int kx = 0; kx < 3; kx++) {
            int gx = xx + kx - 1;
            if (gx < 0 || gx >= WDIM) continue;
            acc += w[oc * 9 + ky * 3 + kx] * g_intensity[(gy << 8) + gx];
        }
    }
    acc = (acc > 0.f) ? acc : 0.2f * acc;
    g_f1[(size_t)oc * L_TOT + l] = acc;
    g_f1o[((size_t)oc * HDIM + y) * OROW + xx + 1] = acc;   // shifted copy, pads stay 0
}

// ---------------- K3: conv2 48->192 (pixel-pair f32x2, E/O bulk-copy staging) ------
// Block: 128 pix x 64 oc, 256 thr. Thread: 4 pix-pairs x 4 oc (oc = oc0 + tx + 16j).
// Ps row layout: [E:0..127 | pad | O:132..263]. E from g_f1 (aligned), O from g_f1o
// (precomputed shift, aligned). Staging = pure float4 copies, no per-elem bounds.
__global__ __launch_bounds__(256, 3) void k_conv2(const float* __restrict__ b2) {
    __shared__ __align__(16) float  Ps[2][3][264];
    __shared__ __align__(16) float2 Ws[2][9][64];
    int tid = threadIdx.x;
    int bid = blockIdx.x;
    int oc0  = (bid % 3) * 64;
    int q    = bid / 3;
    int half = q & 1;
    int y    = q >> 1;
    int x0   = half << 7;
    int tx = tid & 15;
    int ty = tid >> 4;

    u64t acc[4][4];
    #pragma unroll
    for (int i = 0; i < 4; i++)
        #pragma unroll
        for (int j = 0; j < 4; j++) acc[i][j] = 0ull;

    const float4 zero4 = make_float4(0.f, 0.f, 0.f, 0.f);

    auto stage = [&](int ic, int buf) {
        // weights: 9 kp x 64 float2 = 288 float4, contiguous per kp
        for (int idx = tid; idx < 288; idx += 256) {
            int kp = idx >> 5, t = idx & 31;
            ((float4*)&Ws[buf][kp][0])[t] =
                ((const float4*)&g_w2d[(ic * 9 + kp) * 192 + oc0])[t];
        }
        // pixels: 3 rows x (32 E-float4 + 33 O-float4)
        for (int idx = tid; idx < 195; idx += 256) {
            int r = idx / 65, c = idx - r * 65;
            int gy = y + r - 1;
            float4 v = zero4;
            int dst;
            if (c < 32) {
                if (gy >= 0 && gy < HDIM)
                    v = *(const float4*)&g_f1[((size_t)ic * HDIM + gy) * WDIM + x0 + c * 4];
                dst = c * 4;
            } else {
                int co = c - 32;
                if (gy >= 0 && gy < HDIM)
                    v = *(const float4*)&g_f1o[((size_t)ic * HDIM + gy) * OROW + x0 + co * 4];
                dst = 132 + co * 4;
            }
            *(float4*)&Ps[buf][r][dst] = v;
        }
    };

    stage(0, 0);
    __syncthreads();
    for (int ic = 0; ic < C1; ic++) {
        int buf = ic & 1;
        if (ic + 1 < C1) stage(ic + 1, buf ^ 1);
        #pragma unroll
        for (int ky = 0; ky < 3; ky++) {
            const float* E = &Ps[buf][ky][0];
            const float* O = E + 132;
            #pragma unroll
            for (int kx = 0; kx < 3; kx++) {
                int kp = ky * 3 + kx;
                u64t bv[4];
                #pragma unroll
                for (int j = 0; j < 4; j++)
                    bv[j] = *(const u64t*)&Ws[buf][kp][tx + 16 * j];
                const float* ap = (kx == 1) ? E : O;
                int ofs = (kx == 2) ? 2 : 0;
                u64t a[4];
                #pragma unroll
                for (int i = 0; i < 4; i++)
                    a[i] = *(const u64t*)&ap[(ty * 4 + i) * 2 + ofs];
                #pragma unroll
                for (int i = 0; i < 4; i++)
                    #pragma unroll
                    for (int j = 0; j < 4; j++)
                        acc[i][j] = ffma2(a[i], bv[j], acc[i][j]);
            }
        }
        __syncthreads();
    }

    float bj[4];
    #pragma unroll
    for (int j = 0; j < 4; j++) bj[j] = b2[oc0 + tx + 16 * j];
    #pragma unroll
    for (int i = 0; i < 4; i++) {
        int p = (ty * 4 + i) * 2;
        int l = (y << 8) + x0 + p;
        float* op0 = g_feat + (size_t)l * DIM + oc0;
        float* op1 = op0 + DIM;
        #pragma unroll
        for (int j = 0; j < 4; j++) {
            op0[tx + 16 * j] = lo_of(acc[i][j]) + bj[j];
            op1[tx + 16 * j] = hi_of(acc[i][j]) + bj[j];
        }
    }
}

// ---------------- K4: routing MLP + softmax + gumbel argmax (R1-proven) ----------
__global__ __launch_bounds__(256) void k_route(const float* __restrict__ x,
                                               const float* __restrict__ w1,
                                               const float* __restrict__ b1,
                                               const float* __restrict__ w2,
                                               const float* __restrict__ b2r,
                                               const float* __restrict__ gumbel,
                                               const float* __restrict__ emb) {
    __shared__ float z_s[64][17];
    __shared__ float W1s[16][97];
    __shared__ float hm_s[64][97];
    __shared__ float W2s[8][96];
    __shared__ float lg_s[64][9];
    int tid = threadIdx.x;
    int t0base = blockIdx.x * 64;
    int tx = tid & 15;
    int ty = tid >> 4;

    for (int idx = tid; idx < 768; idx += 256)
        W2s[idx / 96][idx % 96] = w2[idx];

    float acc[4][6];
    #pragma unroll
    for (int i = 0; i < 4; i++)
        #pragma unroll
        for (int jj = 0; jj < 6; jj++) acc[i][jj] = 0.f;

    for (int k0 = 0; k0 < DIM; k0 += 16) {
        __syncthreads();
        for (int idx = tid; idx < 1024; idx += 256) {
            int tok = idx >> 4, kk = idx & 15;
            size_t off = (size_t)(t0base + tok) * DIM + k0 + kk;
            z_s[tok][kk] = x[off] + 0.3f * g_feat[off];
        }
        for (int idx = tid; idx < 1536; idx += 256) {
            int j = idx >> 4, kk = idx & 15;
            W1s[kk][j] = w1[j * DIM + k0 + kk];
        }
        __syncthreads();
        #pragma unroll
        for (int kk = 0; kk < 16; kk++) {
            float a[4], b[6];
            #pragma unroll
            for (int i = 0; i < 4; i++) a[i] = z_s[ty * 4 + i][kk];
            #pragma unroll
            for (int jj = 0; jj < 6; jj++) b[jj] = W1s[kk][tx * 6 + jj];
            #pragma unroll
            for (int i = 0; i < 4; i++)
                #pragma unroll
                for (int jj = 0; jj < 6; jj++) acc[i][jj] += a[i] * b[jj];
        }
    }
    __syncthreads();
    #pragma unroll
    for (int jj = 0; jj < 6; jj++) {
        float bb = b1[tx * 6 + jj];
        #pragma unroll
        for (int i = 0; i < 4; i++) {
            float v = acc[i][jj] + bb;
            v = 0.5f * v * (1.0f + erff(v * 0.7071067811865476f));
            hm_s[ty * 4 + i][tx * 6 + jj] = v;
        }
    }
    __syncthreads();
    #pragma unroll
    for (int half = 0; half < 2; half++) {
        int tok = (tid >> 3) + half * 32;
        int t = tid & 7;
        float s = b2r[t];
        #pragma unroll 8
        for (int j = 0; j < 96; j++) s += hm_s[tok][j] * W2s[t][j];
        lg_s[tok][t] = s;
    }
    __syncthreads();
    if (tid < 64) {
        int tok = tid;
        int l = t0base + tok;
        float mx = -1e30f;
        #pragma unroll
        for (int t = 0; t < NTOK; t++) mx = fmaxf(mx, lg_s[tok][t]);
        float e[NTOK], sum = 0.f;
        #pragma unroll
        for (int t = 0; t < NTOK; t++) { e[t] = expf(lg_s[tok][t] - mx); sum += e[t]; }
        float inv = 1.0f / sum;
        float inten = g_intensity[l];
        float best = -1e30f; int kbest = 0; float rw0 = 0.f;
        #pragma unroll
        for (int t = 0; t < NTOK; t++) {
            float rw = e[t] * inv;
            if (t == 0) rw0 = rw;
            float sim = 1.0f - fabsf(emb[t] - inten);
            float u = gumbel[(size_t)l * NTOK + t];
            u = fmaxf(u, 1e-10f);
            float g = -logf(-logf(u));
            float sc = rw * sim + g;
            if (sc > best) { best = sc; kbest = t; }
        }
        float ek = emb[kbest];
        g_gamma[l] = 0.3f + 0.7f / (1.0f + expf(-ek));
        g_beta[l]  = rw0 - 0.5f;
    }
}

// ---------------- K5: v=D*(gamma*x+beta), LayerNorm, out = yn@out_w^T + b ----------
__global__ __launch_bounds__(256, 2) void k_final(const float* __restrict__ x,
                                                  const float* __restrict__ Dv,
                                                  const float* __restrict__ ln_w,
                                                  const float* __restrict__ ln_b,
                                                  const float* __restrict__ out_b,
                                                  float* __restrict__ out) {
    extern __shared__ float sh[];
    float*  v_s  = sh;                           // [64][196]
    u64t*   Bs   = (u64t*)(sh + 64 * 196);       // [16][192]
    float*  mu_s = sh + 64 * 196 + 16 * 192 * 2; // [64]
    float*  rs_s = mu_s + 64;                    // [64]

    int tid = threadIdx.x;
    int l0 = blockIdx.x * 64;
    int tx = tid & 15;
    int ty = tid >> 4;

    for (int idx = tid; idx < 3072; idx += 256) {
        int tok = idx / 48, c4 = idx % 48;
        int l = l0 + tok;
        float4 xv = *(const float4*)&x[(size_t)l * DIM + c4 * 4];
        float4 dv = *(const float4*)&Dv[c4 * 4];
        float g = g_gamma[l], b = g_beta[l];
        float4 v;
        v.x = dv.x * (g * xv.x + b); v.y = dv.y * (g * xv.y + b);
        v.z = dv.z * (g * xv.z + b); v.w = dv.w * (g * xv.w + b);
        *(float4*)&v_s[tok * 196 + c4 * 4] = v;
    }
    __syncthreads();
    {
        int tok = tid >> 2, l4 = tid & 3;
        float s = 0.f, sq = 0.f;
        for (int c = l4; c < DIM; c += 4) {
            float v = v_s[tok * 196 + c];
            s += v; sq += v * v;
        }
        s  += __shfl_down_sync(0xffffffffu, s, 2);
        sq += __shfl_down_sync(0xffffffffu, sq, 2);
        s  += __shfl_down_sync(0xffffffffu, s, 1);
        sq += __shfl_down_sync(0xffffffffu, sq, 1);
        if (l4 == 0) {
            float mu = s * (1.0f / DIM);
            float var = sq * (1.0f / DIM) - mu * mu;
            mu_s[tok] = mu;
            rs_s[tok] = rsqrtf(var + 1e-5f);
        }
    }
    __syncthreads();
    for (int idx = tid; idx < 3072; idx += 256) {
        int tok = idx / 48, c4 = idx % 48;
        float4 v = *(const float4*)&v_s[tok * 196 + c4 * 4];
        float4 lw = *(const float4*)&ln_w[c4 * 4];
        float4 lb = *(const float4*)&ln_b[c4 * 4];
        float mu = mu_s[tok], rs = rs_s[tok];
        v.x = (v.x - mu) * rs * lw.x + lb.x; v.y = (v.y - mu) * rs * lw.y + lb.y;
        v.z = (v.z - mu) * rs * lw.z + lb.z; v.w = (v.w - mu) * rs * lw.w + lb.w;
        *(float4*)&v_s[tok * 196 + c4 * 4] = v;
    }

    u64t acc[4][12];
    #pragma unroll
    for (int i = 0; i < 4; i++)
        #pragma unroll
        for (int j = 0; j < 12; j++) acc[i][j] = 0ull;

    for (int kc = 0; kc < 6; kc++) {
        __syncthreads();
        for (int idx = tid; idx < 3072; idx += 256)
            Bs[idx] = ((const u64t*)g_owt)[kc * 3072 + idx];
        __syncthreads();
        #pragma unroll
        for (int kp = 0; kp < 16; kp++) {
            u64t a[4];
            #pragma unroll
            for (int i = 0; i < 4; i++)
                a[i] = *(const u64t*)&v_s[(ty * 4 + i) * 196 + kc * 32 + kp * 2];
            #pragma unroll
            for (int j = 0; j < 12; j++) {
                u64t bv = Bs[kp * 192 + tx + 16 * j];
                #pragma unroll
                for (int i = 0; i < 4; i++)
                    acc[i][j] = ffma2(a[i], bv, acc[i][j]);
            }
        }
    }

    float bb[12];
    #pragma unroll
    for (int j = 0; j < 12; j++) bb[j] = out_b[tx + 16 * j];
    #pragma unroll
    for (int i = 0; i < 4; i++) {
        int l = l0 + ty * 4 + i;
        float* op = out + (size_t)l * DIM;
        #pragma unroll
        for (int j = 0; j < 12; j++)
            op[tx + 16 * j] = lohi_sum(acc[i][j]) + bb[j];
    }
}

// ---------------- launch ----------------
extern "C" void kernel_launch(void* const* d_in, const int* in_sizes, int n_in,
                              void* d_out, int out_size) {
    const float* x        = (const float*)d_in[0];
    const float* gumbel_u = (const float*)d_in[1];
    const float* conv1_w  = (const float*)d_in[2];
    const float* conv1_b  = (const float*)d_in[3];
    const float* conv2_w  = (const float*)d_in[4];
    const float* conv2_b  = (const float*)d_in[5];
    const float* route1_w = (const float*)d_in[6];
    const float* route1_b = (const float*)d_in[7];
    const float* route2_w = (const float*)d_in[8];
    const float* route2_b = (const float*)d_in[9];
    const float* Dv       = (const float*)d_in[11];
    const float* ln_w     = (const float*)d_in[12];
    const float* ln_b     = (const float*)d_in[13];
    const float* out_w    = (const float*)d_in[14];
    const float* out_b    = (const float*)d_in[15];
    const float* emb      = (const float*)d_in[16];
    float* out = (float*)d_out;

    int final_smem = (64 * 196 + 16 * 192 * 2 + 128 + 16) * (int)sizeof(float);
    static int attr_done = 0;
    if (!attr_done) {
        cudaFuncSetAttribute(k_final, cudaFuncAttributeMaxDynamicSharedMemorySize, final_smem);
        attr_done = 1;
    }

    k_prep<<<(82944 + 18432 + 255) / 256, 256>>>(conv2_w, out_w);
    k_intensity<<<L_TOT / 256, 256>>>(x);
    k_conv1<<<dim3(L_TOT / 256, C1), 256>>>(conv1_w, conv1_b);
    k_conv2<<<6 * HDIM, 256>>>(conv2_b);
    k_route<<<L_TOT / 64, 256>>>(x, route1_w, route1_b, route2_w, route2_b,
                                 gumbel_u, emb);
    k_final<<<L_TOT / 64, 256, final_smem>>>(x, Dv, ln_w, ln_b, out_b, out);
}

// round 12
// speedup vs baseline: 1.8854x; 1.0753x over previous
#include <cuda_runtime.h>
#include <math.h>
#include <stdint.h>

#define L_TOT  65536
#define HDIM   256
#define WDIM   256
#define DIM    192
#define C1     48
#define NTOK   8
#define OROW   260   // padded shifted-row length

typedef unsigned long long u64t;

__device__ __forceinline__ u64t ffma2(u64t a, u64t b, u64t c) {
    u64t d;
    asm("fma.rn.f32x2 %0, %1, %2, %3;" : "=l"(d) : "l"(a), "l"(b), "l"(c));
    return d;
}
union F2u { u64t u; float2 f; };
__device__ __forceinline__ float lohi_sum(u64t v) { F2u t; t.u = v; return t.f.x + t.f.y; }
__device__ __forceinline__ float lo_of(u64t v) { F2u t; t.u = v; return t.f.x; }
__device__ __forceinline__ float hi_of(u64t v) { F2u t; t.u = v; return t.f.y; }

// ---------------- scratch ----------------
__device__ float  g_intensity[L_TOT];
__device__ float  g_f1[(size_t)C1 * L_TOT];          // conv1 out [ic][l] (E rows)
__device__ float  g_f1o[(size_t)C1 * HDIM * OROW];   // conv1 out shifted rows, pads 0
__device__ float  g_feat[(size_t)L_TOT * DIM];       // conv2 out [l][c]
__device__ float  g_gamma[L_TOT];
__device__ float  g_beta[L_TOT];
__device__ float2 g_w2d[432 * 192];                  // conv2 w dup: [k][oc]=(w,w)
__device__ float2 g_owt[96 * 192];                   // out_w k-pairs: [kp][o]
__device__ float2 g_r1t[96 * 96];                    // route1_w k-pairs: [kp][o]=(w1[o][2kp],w1[o][2kp+1])

// ---------------- K0: weight prep ----------------
__global__ void k_prep(const float* __restrict__ w2, const float* __restrict__ out_w,
                       const float* __restrict__ w1) {
    int idx = blockIdx.x * 256 + threadIdx.x;
    if (idx < 82944) {
        int k = idx / 192, oc = idx - k * 192;
        float w = w2[(size_t)oc * 432 + k];
        g_w2d[idx] = make_float2(w, w);
    } else if (idx < 101376) {
        int j = idx - 82944;
        int kp = j / 192, o = j - kp * 192;
        g_owt[j] = make_float2(out_w[o * DIM + kp * 2], out_w[o * DIM + kp * 2 + 1]);
    } else {
        int j = idx - 101376;
        if (j < 9216) {
            int kp = j / 96, o = j - kp * 96;
            g_r1t[j] = make_float2(w1[o * DIM + kp * 2], w1[o * DIM + kp * 2 + 1]);
        }
    }
}

// ---------------- K1: intensity ----------------
__global__ void k_intensity(const float* __restrict__ x) {
    int l = blockIdx.x * 256 + threadIdx.x;
    const float* p = x + (size_t)l * DIM;
    g_intensity[l] = 0.299f * p[0] + 0.587f * p[1] + 0.114f * p[2];
}

// ---------------- K2: conv1 1->48, 3x3 SAME, LeakyReLU(0.2) ----------------
__global__ void k_conv1(const float* __restrict__ w, const float* __restrict__ b) {
    int l  = blockIdx.x * 256 + threadIdx.x;
    int oc = blockIdx.y;
    int y = l >> 8, xx = l & 255;
    float acc = b[oc];
    #pragma unroll
    for (int ky = 0; ky < 3; ky++) {
        int gy = y + ky - 1;
        if (gy < 0 || gy >= HDIM) continue;
        #pragma unroll
        for (int kx = 0; kx < 3; kx++) {
            int gx = xx + kx - 1;
            if (gx < 0 || gx >= WDIM) continue;
            acc += w[oc * 9 + ky * 3 + kx] * g_intensity[(gy << 8) + gx];
        }
    }
    acc = (acc > 0.f) ? acc : 0.2f * acc;
    g_f1[(size_t)oc * L_TOT + l] = acc;
    g_f1o[((size_t)oc * HDIM + y) * OROW + xx + 1] = acc;
}

// ---------------- K3: conv2 48->192 (pixel-pair f32x2, 2 ics per sync) -----------
__global__ __launch_bounds__(256, 3) void k_conv2(const float* __restrict__ b2) {
    __shared__ __align__(16) float  Ps[2][2][3][264];  // [grp-buf][u][row][E|pad|O]
    __shared__ __align__(16) float2 Ws[2][2][9][64];
    int tid = threadIdx.x;
    int bid = blockIdx.x;
    int oc0  = (bid % 3) * 64;
    int q    = bid / 3;
    int half = q & 1;
    int y    = q >> 1;
    int x0   = half << 7;
    int tx = tid & 15;
    int ty = tid >> 4;

    u64t acc[4][4];
    #pragma unroll
    for (int i = 0; i < 4; i++)
        #pragma unroll
        for (int j = 0; j < 4; j++) acc[i][j] = 0ull;

    const float4 zero4 = make_float4(0.f, 0.f, 0.f, 0.f);

    auto stage = [&](int g, int buf) {
        #pragma unroll
        for (int u = 0; u < 2; u++) {
            int ic = g * 2 + u;
            for (int idx = tid; idx < 288; idx += 256) {
                int kp = idx >> 5, t = idx & 31;
                ((float4*)&Ws[buf][u][kp][0])[t] =
                    ((const float4*)&g_w2d[(ic * 9 + kp) * 192 + oc0])[t];
            }
            for (int idx = tid; idx < 195; idx += 256) {
                int r = idx / 65, c = idx - r * 65;
                int gy = y + r - 1;
                float4 v = zero4;
                int dst;
                if (c < 32) {
                    if (gy >= 0 && gy < HDIM)
                        v = *(const float4*)&g_f1[((size_t)ic * HDIM + gy) * WDIM + x0 + c * 4];
                    dst = c * 4;
                } else {
                    int co = c - 32;
                    if (gy >= 0 && gy < HDIM)
                        v = *(const float4*)&g_f1o[((size_t)ic * HDIM + gy) * OROW + x0 + co * 4];
                    dst = 132 + co * 4;
                }
                *(float4*)&Ps[buf][u][r][dst] = v;
            }
        }
    };

    stage(0, 0);
    __syncthreads();
    for (int g = 0; g < 24; g++) {
        int buf = g & 1;
        if (g + 1 < 24) stage(g + 1, buf ^ 1);
        #pragma unroll
        for (int u = 0; u < 2; u++) {
            #pragma unroll
            for (int ky = 0; ky < 3; ky++) {
                const float* E = &Ps[buf][u][ky][0];
                const float* O = E + 132;
                #pragma unroll
                for (int kx = 0; kx < 3; kx++) {
                    int kp = ky * 3 + kx;
                    u64t bv[4];
                    #pragma unroll
                    for (int j = 0; j < 4; j++)
                        bv[j] = *(const u64t*)&Ws[buf][u][kp][tx + 16 * j];
                    const float* ap = (kx == 1) ? E : O;
                    int ofs = (kx == 2) ? 2 : 0;
                    u64t a[4];
                    #pragma unroll
                    for (int i = 0; i < 4; i++)
                        a[i] = *(const u64t*)&ap[(ty * 4 + i) * 2 + ofs];
                    #pragma unroll
                    for (int i = 0; i < 4; i++)
                        #pragma unroll
                        for (int j = 0; j < 4; j++)
                            acc[i][j] = ffma2(a[i], bv[j], acc[i][j]);
                }
            }
        }
        __syncthreads();
    }

    float bj[4];
    #pragma unroll
    for (int j = 0; j < 4; j++) bj[j] = b2[oc0 + tx + 16 * j];
    #pragma unroll
    for (int i = 0; i < 4; i++) {
        int p = (ty * 4 + i) * 2;
        int l = (y << 8) + x0 + p;
        float* op0 = g_feat + (size_t)l * DIM + oc0;
        float* op1 = op0 + DIM;
        #pragma unroll
        for (int j = 0; j < 4; j++) {
            op0[tx + 16 * j] = lo_of(acc[i][j]) + bj[j];
            op1[tx + 16 * j] = hi_of(acc[i][j]) + bj[j];
        }
    }
}

// ---------------- K4: routing MLP (FFMA2 k-pair) + softmax + gumbel argmax -------
// 64 tok/block, 256 thr (tx 0..15, ty 0..15). Thread: 4 tok x 6 hmid (o = tx+16j).
__global__ __launch_bounds__(256, 2) void k_route(const float* __restrict__ x,
                                                  const float* __restrict__ b1,
                                                  const float* __restrict__ w2,
                                                  const float* __restrict__ b2r,
                                                  const float* __restrict__ gumbel,
                                                  const float* __restrict__ emb) {
    extern __shared__ float sh[];
    float* z_s  = sh;                       // [64][196]
    u64t*  W1p  = (u64t*)(sh + 12544);      // [32][96] k-pair dup'd route1 weights
    float* hm_s = sh + 12544 + 6144;        // [64][100]
    float* W2s  = sh + 25088;               // [768]
    float* lg_s = sh + 25856;               // [64][9]

    int tid = threadIdx.x;
    int l0 = blockIdx.x * 64;
    int tx = tid & 15;
    int ty = tid >> 4;

    // stage z = x + 0.3*feat (float4)
    const float4* x4 = (const float4*)(x + (size_t)l0 * DIM);
    const float4* f4 = (const float4*)(g_feat + (size_t)l0 * DIM);
    for (int idx = tid; idx < 3072; idx += 256) {
        int tok = idx / 48, c4 = idx % 48;
        float4 xv = x4[tok * 48 + c4];
        float4 fv = f4[tok * 48 + c4];
        float4 z;
        z.x = xv.x + 0.3f * fv.x; z.y = xv.y + 0.3f * fv.y;
        z.z = xv.z + 0.3f * fv.z; z.w = xv.w + 0.3f * fv.w;
        *(float4*)&z_s[tok * 196 + c4 * 4] = z;
    }
    for (int idx = tid; idx < 768; idx += 256) W2s[idx] = w2[idx];

    u64t acc[4][6];
    #pragma unroll
    for (int i = 0; i < 4; i++)
        #pragma unroll
        for (int j = 0; j < 6; j++) acc[i][j] = 0ull;

    for (int kc = 0; kc < 3; kc++) {
        __syncthreads();
        for (int idx = tid; idx < 3072; idx += 256)
            W1p[idx] = ((const u64t*)g_r1t)[kc * 3072 + idx];
        __syncthreads();
        #pragma unroll 4
        for (int kp = 0; kp < 32; kp++) {
            u64t a[4];
            #pragma unroll
            for (int i = 0; i < 4; i++)
                a[i] = *(const u64t*)&z_s[(ty * 4 + i) * 196 + kc * 64 + kp * 2];
            #pragma unroll
            for (int j = 0; j < 6; j++) {
                u64t bv = W1p[kp * 96 + tx + 16 * j];
                #pragma unroll
                for (int i = 0; i < 4; i++)
                    acc[i][j] = ffma2(a[i], bv, acc[i][j]);
            }
        }
    }
    __syncthreads();
    // GELU epilogue (hmid index = tx + 16j)
    #pragma unroll
    for (int j = 0; j < 6; j++) {
        float bb = b1[tx + 16 * j];
        #pragma unroll
        for (int i = 0; i < 4; i++) {
            float v = lohi_sum(acc[i][j]) + bb;
            v = 0.5f * v * (1.0f + erff(v * 0.7071067811865476f));
            hm_s[(ty * 4 + i) * 100 + tx + 16 * j] = v;
        }
    }
    __syncthreads();
    // route2: (tok, t) pairs
    #pragma unroll
    for (int half = 0; half < 2; half++) {
        int tok = (tid >> 3) + half * 32;
        int t = tid & 7;
        float s = b2r[t];
        const float4* hp = (const float4*)&hm_s[tok * 100];
        const float4* wp = (const float4*)&W2s[t * 96];
        #pragma unroll 6
        for (int j4 = 0; j4 < 24; j4++) {
            float4 h = hp[j4], w = wp[j4];
            s += h.x * w.x + h.y * w.y + h.z * w.z + h.w * w.w;
        }
        lg_s[tok * 9 + t] = s;
    }
    __syncthreads();
    if (tid < 64) {
        int tok = tid;
        int l = l0 + tok;
        float mx = -1e30f;
        #pragma unroll
        for (int t = 0; t < NTOK; t++) mx = fmaxf(mx, lg_s[tok * 9 + t]);
        float e[NTOK], sum = 0.f;
        #pragma unroll
        for (int t = 0; t < NTOK; t++) { e[t] = expf(lg_s[tok * 9 + t] - mx); sum += e[t]; }
        float inv = 1.0f / sum;
        float inten = g_intensity[l];
        float best = -1e30f; int kbest = 0; float rw0 = 0.f;
        #pragma unroll
        for (int t = 0; t < NTOK; t++) {
            float rw = e[t] * inv;
            if (t == 0) rw0 = rw;
            float sim = 1.0f - fabsf(emb[t] - inten);
            float u = gumbel[(size_t)l * NTOK + t];
            u = fmaxf(u, 1e-10f);
            float g = -logf(-logf(u));
            float sc = rw * sim + g;
            if (sc > best) { best = sc; kbest = t; }
        }
        float ek = emb[kbest];
        g_gamma[l] = 0.3f + 0.7f / (1.0f + expf(-ek));
        g_beta[l]  = rw0 - 0.5f;
    }
}

// ---------------- K5: v=D*(gamma*x+beta), LayerNorm, out = yn@out_w^T + b ----------
__global__ __launch_bounds__(256, 2) void k_final(const float* __restrict__ x,
                                                  const float* __restrict__ Dv,
                                                  const float* __restrict__ ln_w,
                                                  const float* __restrict__ ln_b,
                                                  const float* __restrict__ out_b,
                                                  float* __restrict__ out) {
    extern __shared__ float sh[];
    float*  v_s  = sh;                           // [64][196]
    u64t*   Bs   = (u64t*)(sh + 64 * 196);       // [16][192]
    float*  mu_s = sh + 64 * 196 + 16 * 192 * 2; // [64]
    float*  rs_s = mu_s + 64;                    // [64]

    int tid = threadIdx.x;
    int l0 = blockIdx.x * 64;
    int tx = tid & 15;
    int ty = tid >> 4;

    for (int idx = tid; idx < 3072; idx += 256) {
        int tok = idx / 48, c4 = idx % 48;
        int l = l0 + tok;
        float4 xv = *(const float4*)&x[(size_t)l * DIM + c4 * 4];
        float4 dv = *(const float4*)&Dv[c4 * 4];
        float g = g_gamma[l], b = g_beta[l];
        float4 v;
        v.x = dv.x * (g * xv.x + b); v.y = dv.y * (g * xv.y + b);
        v.z = dv.z * (g * xv.z + b); v.w = dv.w * (g * xv.w + b);
        *(float4*)&v_s[tok * 196 + c4 * 4] = v;
    }
    __syncthreads();
    {
        int tok = tid >> 2, l4 = tid & 3;
        float s = 0.f, sq = 0.f;
        for (int c = l4; c < DIM; c += 4) {
            float v = v_s[tok * 196 + c];
            s += v; sq += v * v;
        }
        s  += __shfl_down_sync(0xffffffffu, s, 2);
        sq += __shfl_down_sync(0xffffffffu, sq, 2);
        s  += __shfl_down_sync(0xffffffffu, s, 1);
        sq += __shfl_down_sync(0xffffffffu, sq, 1);
        if (l4 == 0) {
            float mu = s * (1.0f / DIM);
            float var = sq * (1.0f / DIM) - mu * mu;
            mu_s[tok] = mu;
            rs_s[tok] = rsqrtf(var + 1e-5f);
        }
    }
    __syncthreads();
    for (int idx = tid; idx < 3072; idx += 256) {
        int tok = idx / 48, c4 = idx % 48;
        float4 v = *(const float4*)&v_s[tok * 196 + c4 * 4];
        float4 lw = *(const float4*)&ln_w[c4 * 4];
        float4 lb = *(const float4*)&ln_b[c4 * 4];
        float mu = mu_s[tok], rs = rs_s[tok];
        v.x = (v.x - mu) * rs * lw.x + lb.x; v.y = (v.y - mu) * rs * lw.y + lb.y;
        v.z = (v.z - mu) * rs * lw.z + lb.z; v.w = (v.w - mu) * rs * lw.w + lb.w;
        *(float4*)&v_s[tok * 196 + c4 * 4] = v;
    }

    u64t acc[4][12];
    #pragma unroll
    for (int i = 0; i < 4; i++)
        #pragma unroll
        for (int j = 0; j < 12; j++) acc[i][j] = 0ull;

    for (int kc = 0; kc < 6; kc++) {
        __syncthreads();
        for (int idx = tid; idx < 3072; idx += 256)
            Bs[idx] = ((const u64t*)g_owt)[kc * 3072 + idx];
        __syncthreads();
        #pragma unroll
        for (int kp = 0; kp < 16; kp++) {
            u64t a[4];
            #pragma unroll
            for (int i = 0; i < 4; i++)
                a[i] = *(const u64t*)&v_s[(ty * 4 + i) * 196 + kc * 32 + kp * 2];
            #pragma unroll
            for (int j = 0; j < 12; j++) {
                u64t bv = Bs[kp * 192 + tx + 16 * j];
                #pragma unroll
                for (int i = 0; i < 4; i++)
                    acc[i][j] = ffma2(a[i], bv, acc[i][j]);
            }
        }
    }

    float bb[12];
    #pragma unroll
    for (int j = 0; j < 12; j++) bb[j] = out_b[tx + 16 * j];
    #pragma unroll
    for (int i = 0; i < 4; i++) {
        int l = l0 + ty * 4 + i;
        float* op = out + (size_t)l * DIM;
        #pragma unroll
        for (int j = 0; j < 12; j++)
            op[tx + 16 * j] = lohi_sum(acc[i][j]) + bb[j];
    }
}

// ---------------- launch ----------------
extern "C" void kernel_launch(void* const* d_in, const int* in_sizes, int n_in,
                              void* d_out, int out_size) {
    const float* x        = (const float*)d_in[0];
    const float* gumbel_u = (const float*)d_in[1];
    const float* conv1_w  = (const float*)d_in[2];
    const float* conv1_b  = (const float*)d_in[3];
    const float* conv2_w  = (const float*)d_in[4];
    const float* conv2_b  = (const float*)d_in[5];
    const float* route1_w = (const float*)d_in[6];
    const float* route1_b = (const float*)d_in[7];
    const float* route2_w = (const float*)d_in[8];
    const float* route2_b = (const float*)d_in[9];
    const float* Dv       = (const float*)d_in[11];
    const float* ln_w     = (const float*)d_in[12];
    const float* ln_b     = (const float*)d_in[13];
    const float* out_w    = (const float*)d_in[14];
    const float* out_b    = (const float*)d_in[15];
    const float* emb      = (const float*)d_in[16];
    float* out = (float*)d_out;

    int route_smem = (25856 + 576 + 32) * (int)sizeof(float);
    int final_smem = (64 * 196 + 16 * 192 * 2 + 128 + 16) * (int)sizeof(float);
    static int attr_done = 0;
    if (!attr_done) {
        cudaFuncSetAttribute(k_route, cudaFuncAttributeMaxDynamicSharedMemorySize, route_smem);
        cudaFuncSetAttribute(k_final, cudaFuncAttributeMaxDynamicSharedMemorySize, final_smem);
        attr_done = 1;
    }

    k_prep<<<(82944 + 18432 + 9216 + 255) / 256, 256>>>(conv2_w, out_w, route1_w);
    k_intensity<<<L_TOT / 256, 256>>>(x);
    k_conv1<<<dim3(L_TOT / 256, C1), 256>>>(conv1_w, conv1_b);
    k_conv2<<<6 * HDIM, 256>>>(conv2_b);
    k_route<<<L_TOT / 64, 256, route_smem>>>(x, route1_b, route2_w, route2_b,
                                             gumbel_u, emb);
    k_final<<<L_TOT / 64, 256, final_smem>>>(x, Dv, ln_w, ln_b, out_b, out);
}

// round 13
// speedup vs baseline: 1.8904x; 1.0026x over previous
#include <cuda_runtime.h>
#include <math.h>
#include <stdint.h>

#define L_TOT  65536
#define HDIM   256
#define WDIM   256
#define DIM    192
#define C1     48
#define NTOK   8
#define OROW   260   // padded shifted-row length

typedef unsigned long long u64t;

__device__ __forceinline__ u64t ffma2(u64t a, u64t b, u64t c) {
    u64t d;
    asm("fma.rn.f32x2 %0, %1, %2, %3;" : "=l"(d) : "l"(a), "l"(b), "l"(c));
    return d;
}
union F2u { u64t u; float2 f; };
__device__ __forceinline__ float lohi_sum(u64t v) { F2u t; t.u = v; return t.f.x + t.f.y; }
__device__ __forceinline__ float lo_of(u64t v) { F2u t; t.u = v; return t.f.x; }
__device__ __forceinline__ float hi_of(u64t v) { F2u t; t.u = v; return t.f.y; }

// ---------------- scratch ----------------
__device__ float  g_intensity[L_TOT];
__device__ float  g_f1[(size_t)C1 * L_TOT];          // conv1 out [ic][l] (E rows)
__device__ float  g_f1o[(size_t)C1 * HDIM * OROW];   // conv1 out shifted rows, pads 0
__device__ float  g_feat[(size_t)L_TOT * DIM];       // conv2 out [l][c]
__device__ float  g_gamma[L_TOT];
__device__ float  g_beta[L_TOT];
// conv2 dup weights, paired layout: [((ic*9+kp)*3+g)][pair(2)][tx(16)][jj(2)], oc=g*64+tx+16*(2*pair+jj)
__device__ float2 g_w2d[432 * 192];
// out_w k-pairs, paired layout: [((kc*16+kp)*6+pair)][tx(16)][jj(2)], o=tx+16*(2*pair+jj)
__device__ float2 g_owt[96 * 192];
// route1_w k-pairs, paired layout: [((kc*32+kp)*3+pair)][tx(16)][jj(2)]
__device__ float2 g_r1t[96 * 96];

// ---------------- K0: weight prep ----------------
__global__ void k_prep(const float* __restrict__ w2, const float* __restrict__ out_w,
                       const float* __restrict__ w1) {
    int idx = blockIdx.x * 256 + threadIdx.x;
    if (idx < 82944) {
        int lane = idx & 63, chunk = idx >> 6;
        int g = chunk % 3, t2 = chunk / 3;
        int kp = t2 % 9, ic = t2 / 9;
        int pair = lane >> 5, r = lane & 31;
        int tx = r >> 1, jj = r & 1;
        int oc = g * 64 + tx + 16 * (2 * pair + jj);
        float w = w2[(size_t)oc * 432 + ic * 9 + kp];
        g_w2d[idx] = make_float2(w, w);
    } else if (idx < 101376) {
        int j = idx - 82944;
        int lane = j & 31, t = j >> 5;
        int tx = lane >> 1, jj = lane & 1;
        int pair = t % 6, t2 = t / 6;
        int kp = t2 % 16, kc = t2 / 16;
        int o = tx + 16 * (2 * pair + jj);
        int kk = kc * 32 + kp * 2;
        g_owt[j] = make_float2(out_w[o * DIM + kk], out_w[o * DIM + kk + 1]);
    } else {
        int j = idx - 101376;
        if (j < 9216) {
            int lane = j & 31, t = j >> 5;
            int tx = lane >> 1, jj = lane & 1;
            int pair = t % 3, t2 = t / 3;
            int kp = t2 % 32, kc = t2 / 32;
            int o = tx + 16 * (2 * pair + jj);
            int kk = kc * 64 + kp * 2;
            g_r1t[j] = make_float2(w1[o * DIM + kk], w1[o * DIM + kk + 1]);
        }
    }
}

// ---------------- K1: intensity ----------------
__global__ void k_intensity(const float* __restrict__ x) {
    int l = blockIdx.x * 256 + threadIdx.x;
    const float* p = x + (size_t)l * DIM;
    g_intensity[l] = 0.299f * p[0] + 0.587f * p[1] + 0.114f * p[2];
}

// ---------------- K2: conv1 1->48, 3x3 SAME, LeakyReLU(0.2) ----------------
__global__ void k_conv1(const float* __restrict__ w, const float* __restrict__ b) {
    int l  = blockIdx.x * 256 + threadIdx.x;
    int oc = blockIdx.y;
    int y = l >> 8, xx = l & 255;
    float acc = b[oc];
    #pragma unroll
    for (int ky = 0; ky < 3; ky++) {
        int gy = y + ky - 1;
        if (gy < 0 || gy >= HDIM) continue;
        #pragma unroll
        for (int kx = 0; kx < 3; kx++) {
            int gx = xx + kx - 1;
            if (gx < 0 || gx >= WDIM) continue;
            acc += w[oc * 9 + ky * 3 + kx] * g_intensity[(gy << 8) + gx];
        }
    }
    acc = (acc > 0.f) ? acc : 0.2f * acc;
    g_f1[(size_t)oc * L_TOT + l] = acc;
    g_f1o[((size_t)oc * HDIM + y) * OROW + xx + 1] = acc;
}

// ---------------- K3: conv2 48->192 (pixel-pair f32x2, LDS.128 b, a-reuse) -------
__global__ __launch_bounds__(256, 3) void k_conv2(const float* __restrict__ b2) {
    __shared__ __align__(16) float  Ps[2][2][3][264];  // [grp-buf][u][row][E|pad|O]
    __shared__ __align__(16) float2 Ws[2][2][9][64];   // paired layout per kp
    int tid = threadIdx.x;
    int bid = blockIdx.x;
    int oc0  = (bid % 3) * 64;
    int q    = bid / 3;
    int half = q & 1;
    int y    = q >> 1;
    int x0   = half << 7;
    int tx = tid & 15;
    int ty = tid >> 4;

    u64t acc[4][4];
    #pragma unroll
    for (int i = 0; i < 4; i++)
        #pragma unroll
        for (int j = 0; j < 4; j++) acc[i][j] = 0ull;

    const float4 zero4 = make_float4(0.f, 0.f, 0.f, 0.f);
    int gsel = bid % 3;

    auto stage = [&](int g, int buf) {
        #pragma unroll
        for (int u = 0; u < 2; u++) {
            int ic = g * 2 + u;
            for (int idx = tid; idx < 288; idx += 256) {
                int kp = idx >> 5, t = idx & 31;
                ((float4*)&Ws[buf][u][kp][0])[t] =
                    ((const float4*)&g_w2d[((ic * 9 + kp) * 3 + gsel) * 64])[t];
            }
            for (int idx = tid; idx < 195; idx += 256) {
                int r = idx / 65, c = idx - r * 65;
                int gy = y + r - 1;
                float4 v = zero4;
                int dst;
                if (c < 32) {
                    if (gy >= 0 && gy < HDIM)
                        v = *(const float4*)&g_f1[((size_t)ic * HDIM + gy) * WDIM + x0 + c * 4];
                    dst = c * 4;
                } else {
                    int co = c - 32;
                    if (gy >= 0 && gy < HDIM)
                        v = *(const float4*)&g_f1o[((size_t)ic * HDIM + gy) * OROW + x0 + co * 4];
                    dst = 132 + co * 4;
                }
                *(float4*)&Ps[buf][u][r][dst] = v;
            }
        }
    };

    stage(0, 0);
    __syncthreads();
    for (int g = 0; g < 24; g++) {
        int buf = g & 1;
        if (g + 1 < 24) stage(g + 1, buf ^ 1);
        #pragma unroll
        for (int u = 0; u < 2; u++) {
            #pragma unroll
            for (int ky = 0; ky < 3; ky++) {
                const float* E = &Ps[buf][u][ky][0];
                const float* O = E + 132;
                u64t Er[4], Or[5];
                #pragma unroll
                for (int i = 0; i < 4; i++)
                    Er[i] = *(const u64t*)&E[(ty * 4 + i) * 2];
                #pragma unroll
                for (int i = 0; i < 5; i++)
                    Or[i] = *(const u64t*)&O[(ty * 4 + i) * 2];
                #pragma unroll
                for (int kx = 0; kx < 3; kx++) {
                    int kp = ky * 3 + kx;
                    const ulonglong2* wp = (const ulonglong2*)&Ws[buf][u][kp][0];
                    ulonglong2 w01 = wp[tx];
                    ulonglong2 w23 = wp[16 + tx];
                    u64t bv[4] = {w01.x, w01.y, w23.x, w23.y};
                    #pragma unroll
                    for (int i = 0; i < 4; i++) {
                        u64t a = (kx == 1) ? Er[i] : ((kx == 0) ? Or[i] : Or[i + 1]);
                        #pragma unroll
                        for (int j = 0; j < 4; j++)
                            acc[i][j] = ffma2(a, bv[j], acc[i][j]);
                    }
                }
            }
        }
        __syncthreads();
    }

    float bj[4];
    #pragma unroll
    for (int j = 0; j < 4; j++) bj[j] = b2[oc0 + tx + 16 * j];
    #pragma unroll
    for (int i = 0; i < 4; i++) {
        int p = (ty * 4 + i) * 2;
        int l = (y << 8) + x0 + p;
        float* op0 = g_feat + (size_t)l * DIM + oc0;
        float* op1 = op0 + DIM;
        #pragma unroll
        for (int j = 0; j < 4; j++) {
            op0[tx + 16 * j] = lo_of(acc[i][j]) + bj[j];
            op1[tx + 16 * j] = hi_of(acc[i][j]) + bj[j];
        }
    }
}

// ---------------- K4: routing MLP (FFMA2 k-pair, LDS.128 b) + gumbel argmax ------
__global__ __launch_bounds__(256, 2) void k_route(const float* __restrict__ x,
                                                  const float* __restrict__ b1,
                                                  const float* __restrict__ w2,
                                                  const float* __restrict__ b2r,
                                                  const float* __restrict__ gumbel,
                                                  const float* __restrict__ emb) {
    extern __shared__ float sh[];
    float* z_s  = sh;                       // [64][196]
    u64t*  W1p  = (u64t*)(sh + 12544);      // [32][96] paired layout
    float* hm_s = sh + 12544 + 6144;        // [64][100]
    float* W2s  = sh + 25088;               // [768]
    float* lg_s = sh + 25856;               // [64][9]

    int tid = threadIdx.x;
    int l0 = blockIdx.x * 64;
    int tx = tid & 15;
    int ty = tid >> 4;

    const float4* x4 = (const float4*)(x + (size_t)l0 * DIM);
    const float4* f4 = (const float4*)(g_feat + (size_t)l0 * DIM);
    for (int idx = tid; idx < 3072; idx += 256) {
        int tok = idx / 48, c4 = idx % 48;
        float4 xv = x4[tok * 48 + c4];
        float4 fv = f4[tok * 48 + c4];
        float4 z;
        z.x = xv.x + 0.3f * fv.x; z.y = xv.y + 0.3f * fv.y;
        z.z = xv.z + 0.3f * fv.z; z.w = xv.w + 0.3f * fv.w;
        *(float4*)&z_s[tok * 196 + c4 * 4] = z;
    }
    for (int idx = tid; idx < 768; idx += 256) W2s[idx] = w2[idx];

    u64t acc[4][6];
    #pragma unroll
    for (int i = 0; i < 4; i++)
        #pragma unroll
        for (int j = 0; j < 6; j++) acc[i][j] = 0ull;

    for (int kc = 0; kc < 3; kc++) {
        __syncthreads();
        for (int idx = tid; idx < 3072; idx += 256)
            W1p[idx] = ((const u64t*)g_r1t)[kc * 3072 + idx];
        __syncthreads();
        #pragma unroll 4
        for (int kp = 0; kp < 32; kp++) {
            u64t a[4];
            #pragma unroll
            for (int i = 0; i < 4; i++)
                a[i] = *(const u64t*)&z_s[(ty * 4 + i) * 196 + kc * 64 + kp * 2];
            const ulonglong2* wp = (const ulonglong2*)&W1p[kp * 96];
            u64t bv[6];
            #pragma unroll
            for (int p = 0; p < 3; p++) {
                ulonglong2 w = wp[p * 16 + tx];
                bv[2 * p] = w.x; bv[2 * p + 1] = w.y;
            }
            #pragma unroll
            for (int j = 0; j < 6; j++)
                #pragma unroll
                for (int i = 0; i < 4; i++)
                    acc[i][j] = ffma2(a[i], bv[j], acc[i][j]);
        }
    }
    __syncthreads();
    #pragma unroll
    for (int j = 0; j < 6; j++) {
        float bb = b1[tx + 16 * j];
        #pragma unroll
        for (int i = 0; i < 4; i++) {
            float v = lohi_sum(acc[i][j]) + bb;
            v = 0.5f * v * (1.0f + erff(v * 0.7071067811865476f));
            hm_s[(ty * 4 + i) * 100 + tx + 16 * j] = v;
        }
    }
    __syncthreads();
    #pragma unroll
    for (int half = 0; half < 2; half++) {
        int tok = (tid >> 3) + half * 32;
        int t = tid & 7;
        float s = b2r[t];
        const float4* hp = (const float4*)&hm_s[tok * 100];
        const float4* wp = (const float4*)&W2s[t * 96];
        #pragma unroll 6
        for (int j4 = 0; j4 < 24; j4++) {
            float4 h = hp[j4], w = wp[j4];
            s += h.x * w.x + h.y * w.y + h.z * w.z + h.w * w.w;
        }
        lg_s[tok * 9 + t] = s;
    }
    __syncthreads();
    if (tid < 64) {
        int tok = tid;
        int l = l0 + tok;
        float mx = -1e30f;
        #pragma unroll
        for (int t = 0; t < NTOK; t++) mx = fmaxf(mx, lg_s[tok * 9 + t]);
        float e[NTOK], sum = 0.f;
        #pragma unroll
        for (int t = 0; t < NTOK; t++) { e[t] = expf(lg_s[tok * 9 + t] - mx); sum += e[t]; }
        float inv = 1.0f / sum;
        float inten = g_intensity[l];
        float best = -1e30f; int kbest = 0; float rw0 = 0.f;
        #pragma unroll
        for (int t = 0; t < NTOK; t++) {
            float rw = e[t] * inv;
            if (t == 0) rw0 = rw;
            float sim = 1.0f - fabsf(emb[t] - inten);
            float u = gumbel[(size_t)l * NTOK + t];
            u = fmaxf(u, 1e-10f);
            float g = -logf(-logf(u));
            float sc = rw * sim + g;
            if (sc > best) { best = sc; kbest = t; }
        }
        float ek = emb[kbest];
        g_gamma[l] = 0.3f + 0.7f / (1.0f + expf(-ek));
        g_beta[l]  = rw0 - 0.5f;
    }
}

// ---------------- K5: v=D*(gamma*x+beta), LayerNorm, out (LDS.128 b) -------------
__global__ __launch_bounds__(256, 2) void k_final(const float* __restrict__ x,
                                                  const float* __restrict__ Dv,
                                                  const float* __restrict__ ln_w,
                                                  const float* __restrict__ ln_b,
                                                  const float* __restrict__ out_b,
                                                  float* __restrict__ out) {
    extern __shared__ float sh[];
    float*  v_s  = sh;                           // [64][196]
    u64t*   Bs   = (u64t*)(sh + 64 * 196);       // [16][192] paired layout
    float*  mu_s = sh + 64 * 196 + 16 * 192 * 2; // [64]
    float*  rs_s = mu_s + 64;                    // [64]

    int tid = threadIdx.x;
    int l0 = blockIdx.x * 64;
    int tx = tid & 15;
    int ty = tid >> 4;

    for (int idx = tid; idx < 3072; idx += 256) {
        int tok = idx / 48, c4 = idx % 48;
        int l = l0 + tok;
        float4 xv = *(const float4*)&x[(size_t)l * DIM + c4 * 4];
        float4 dv = *(const float4*)&Dv[c4 * 4];
        float g = g_gamma[l], b = g_beta[l];
        float4 v;
        v.x = dv.x * (g * xv.x + b); v.y = dv.y * (g * xv.y + b);
        v.z = dv.z * (g * xv.z + b); v.w = dv.w * (g * xv.w + b);
        *(float4*)&v_s[tok * 196 + c4 * 4] = v;
    }
    __syncthreads();
    {
        int tok = tid >> 2, l4 = tid & 3;
        float s = 0.f, sq = 0.f;
        for (int c = l4; c < DIM; c += 4) {
            float v = v_s[tok * 196 + c];
            s += v; sq += v * v;
        }
        s  += __shfl_down_sync(0xffffffffu, s, 2);
        sq += __shfl_down_sync(0xffffffffu, sq, 2);
        s  += __shfl_down_sync(0xffffffffu, s, 1);
        sq += __shfl_down_sync(0xffffffffu, sq, 1);
        if (l4 == 0) {
            float mu = s * (1.0f / DIM);
            float var = sq * (1.0f / DIM) - mu * mu;
            mu_s[tok] = mu;
            rs_s[tok] = rsqrtf(var + 1e-5f);
        }
    }
    __syncthreads();
    for (int idx = tid; idx < 3072; idx += 256) {
        int tok = idx / 48, c4 = idx % 48;
        float4 v = *(const float4*)&v_s[tok * 196 + c4 * 4];
        float4 lw = *(const float4*)&ln_w[c4 * 4];
        float4 lb = *(const float4*)&ln_b[c4 * 4];
        float mu = mu_s[tok], rs = rs_s[tok];
        v.x = (v.x - mu) * rs * lw.x + lb.x; v.y = (v.y - mu) * rs * lw.y + lb.y;
        v.z = (v.z - mu) * rs * lw.z + lb.z; v.w = (v.w - mu) * rs * lw.w + lb.w;
        *(float4*)&v_s[tok * 196 + c4 * 4] = v;
    }

    u64t acc[4][12];
    #pragma unroll
    for (int i = 0; i < 4; i++)
        #pragma unroll
        for (int j = 0; j < 12; j++) acc[i][j] = 0ull;

    for (int kc = 0; kc < 6; kc++) {
        __syncthreads();
        for (int idx = tid; idx < 3072; idx += 256)
            Bs[idx] = ((const u64t*)g_owt)[kc * 3072 + idx];
        __syncthreads();
        #pragma unroll
        for (int kp = 0; kp < 16; kp++) {
            u64t a[4];
            #pragma unroll
            for (int i = 0; i < 4; i++)
                a[i] = *(const u64t*)&v_s[(ty * 4 + i) * 196 + kc * 32 + kp * 2];
            const ulonglong2* wp = (const ulonglong2*)&Bs[kp * 192];
            u64t bv[12];
            #pragma unroll
            for (int p = 0; p < 6; p++) {
                ulonglong2 w = wp[p * 16 + tx];
                bv[2 * p] = w.x; bv[2 * p + 1] = w.y;
            }
            #pragma unroll
            for (int j = 0; j < 12; j++)
                #pragma unroll
                for (int i = 0; i < 4; i++)
                    acc[i][j] = ffma2(a[i], bv[j], acc[i][j]);
        }
    }

    float bb[12];
    #pragma unroll
    for (int j = 0; j < 12; j++) bb[j] = out_b[tx + 16 * j];
    #pragma unroll
    for (int i = 0; i < 4; i++) {
        int l = l0 + ty * 4 + i;
        float* op = out + (size_t)l * DIM;
        #pragma unroll
        for (int j = 0; j < 12; j++)
            op[tx + 16 * j] = lohi_sum(acc[i][j]) + bb[j];
    }
}

// ---------------- launch ----------------
extern "C" void kernel_launch(void* const* d_in, const int* in_sizes, int n_in,
                              void* d_out, int out_size) {
    const float* x        = (const float*)d_in[0];
    const float* gumbel_u = (const float*)d_in[1];
    const float* conv1_w  = (const float*)d_in[2];
    const float* conv1_b  = (const float*)d_in[3];
    const float* conv2_w  = (const float*)d_in[4];
    const float* conv2_b  = (const float*)d_in[5];
    const float* route1_w = (const float*)d_in[6];
    const float* route1_b = (const float*)d_in[7];
    const float* route2_w = (const float*)d_in[8];
    const float* route2_b = (const float*)d_in[9];
    const float* Dv       = (const float*)d_in[11];
    const float* ln_w     = (const float*)d_in[12];
    const float* ln_b     = (const float*)d_in[13];
    const float* out_w    = (const float*)d_in[14];
    const float* out_b    = (const float*)d_in[15];
    const float* emb      = (const float*)d_in[16];
    float* out = (float*)d_out;

    int route_smem = (25856 + 576 + 32) * (int)sizeof(float);
    int final_smem = (64 * 196 + 16 * 192 * 2 + 128 + 16) * (int)sizeof(float);
    static int attr_done = 0;
    if (!attr_done) {
        cudaFuncSetAttribute(k_route, cudaFuncAttributeMaxDynamicSharedMemorySize, route_smem);
        cudaFuncSetAttribute(k_final, cudaFuncAttributeMaxDynamicSharedMemorySize, final_smem);
        attr_done = 1;
    }

    k_prep<<<(82944 + 18432 + 9216 + 255) / 256, 256>>>(conv2_w, out_w, route1_w);
    k_intensity<<<L_TOT / 256, 256>>>(x);
    k_conv1<<<dim3(L_TOT / 256, C1), 256>>>(conv1_w, conv1_b);
    k_conv2<<<6 * HDIM, 256>>>(conv2_b);
    k_route<<<L_TOT / 64, 256, route_smem>>>(x, route1_b, route2_w, route2_b,
                                             gumbel_u, emb);
    k_final<<<L_TOT / 64, 256, final_smem>>>(x, Dv, ln_w, ln_b, out_b, out);
}